// round 6
// baseline (speedup 1.0000x reference)
#include <cuda_runtime.h>
#include <stdint.h>

#define N_NODES 50000
#define N_EDGES 600000
#define IN_DIM  16
#define HID     128
#define OUT_DIM 4
#define NT_GEMM ((N_NODES + 63) / 64)   // 782 row-tiles of 64

// ---------------- device scratch (no runtime allocation allowed) ----------------
__device__ int   g_deg[N_NODES];
__device__ int   g_cur[N_NODES];
__device__ int   g_off[N_NODES + 1];
__device__ int   g_esrc[N_EDGES];
__device__ float g_invdeg[N_NODES];
__device__ float g_agg[N_NODES * HID];
__device__ float g_hA[N_NODES * HID];
__device__ float g_hB[N_NODES * HID];
__device__ int   g_is64;

// ---------------- dtype detection for edge_index (int64 vs int32) ----------------
__global__ void k_detect(const unsigned int* __restrict__ ei32) {
    // If edge_index is int64 (little-endian, node ids < 2^31), every odd 32-bit word is 0.
    if (threadIdx.x == 0) {
        unsigned int acc = 0;
        #pragma unroll
        for (int i = 0; i < 64; i++) acc |= ei32[2 * i + 1];
        g_is64 = (acc == 0) ? 1 : 0;
    }
}

__device__ __forceinline__ int load_edge(const void* ei, int idx, int is64) {
    if (is64) return (int)((const long long*)ei)[idx];
    return ((const int*)ei)[idx];
}

// ---------------- CSR build ----------------
__global__ void k_zero() {
    int i = blockIdx.x * blockDim.x + threadIdx.x;
    if (i < N_NODES) { g_deg[i] = 0; g_cur[i] = 0; }
}

__global__ void k_count(const void* __restrict__ ei) {
    int e = blockIdx.x * blockDim.x + threadIdx.x;
    if (e >= N_EDGES) return;
    int is64 = g_is64;
    int d = load_edge(ei, N_EDGES + e, is64);
    if ((unsigned)d < (unsigned)N_NODES)     // clamp: never OOB
        atomicAdd(&g_deg[d], 1);
}

// 512-thread hierarchical prefix scan over g_deg -> g_off (exclusive)
__global__ void k_scan() {
    __shared__ int wsum[16];
    __shared__ int carry;
    int t = threadIdx.x, lane = t & 31, w = t >> 5;   // 16 warps
    if (t == 0) carry = 0;
    __syncthreads();
    for (int base = 0; base < N_NODES; base += 512) {
        int i = base + t;
        int v = (i < N_NODES) ? g_deg[i] : 0;
        int x = v;
        #pragma unroll
        for (int d = 1; d < 32; d <<= 1) {
            int y = __shfl_up_sync(0xffffffffu, x, d);
            if (lane >= d) x += y;
        }
        if (lane == 31) wsum[w] = x;
        __syncthreads();
        if (t < 16) {
            int s = wsum[t];
            int xs = s;
            #pragma unroll
            for (int d = 1; d < 16; d <<= 1) {
                int y = __shfl_up_sync(0x0000ffffu, xs, d);
                if (t >= d) xs += y;
            }
            wsum[t] = xs - s;   // exclusive prefix over warp totals
        }
        __syncthreads();
        int excl = carry + wsum[w] + (x - v);
        if (i < N_NODES) g_off[i] = excl;
        __syncthreads();
        if (t == 511) carry += wsum[15] + x;
        __syncthreads();
    }
    if (t == 0) g_off[N_NODES] = carry;
}

__global__ void k_invdeg() {
    int i = blockIdx.x * blockDim.x + threadIdx.x;
    if (i < N_NODES) {
        int d = g_deg[i];
        g_invdeg[i] = 1.0f / (float)(d > 0 ? d : 1);
    }
}

__global__ void k_fill(const void* __restrict__ ei) {
    int e = blockIdx.x * blockDim.x + threadIdx.x;
    if (e >= N_EDGES) return;
    int is64 = g_is64;
    int d = load_edge(ei, N_EDGES + e, is64);
    if ((unsigned)d >= (unsigned)N_NODES) return;   // consistent with k_count
    int s = load_edge(ei, e, is64);
    if ((unsigned)s >= (unsigned)N_NODES) s = 0;    // clamp: never OOB
    int p = g_off[d] + atomicAdd(&g_cur[d], 1);
    if ((unsigned)p < (unsigned)N_EDGES)
        g_esrc[p] = s;
}

// ---------------- layer 1: aggregate x (16-d) + dual GEMM 16->128 + relu ----------------
__global__ void k_layer1(const float* __restrict__ x,
                         const float* __restrict__ Wl,
                         const float* __restrict__ Wr,
                         const float* __restrict__ b,
                         float* __restrict__ hout) {
    __shared__ float sWl[IN_DIM * HID], sWr[IN_DIM * HID], sb[HID];
    __shared__ float red[128], sagg[IN_DIM], sx[IN_DIM];
    int t = threadIdx.x;
    for (int i = t; i < HID * IN_DIM; i += 128) {
        int o = i >> 4, k = i & 15;
        sWl[k * HID + o] = Wl[i];   // sW[k][o] = W[o][k]
        sWr[k * HID + o] = Wr[i];
    }
    sb[t] = b[t];
    __syncthreads();
    int k = t & 15, s = t >> 4;
    for (int n = blockIdx.x; n < N_NODES; n += gridDim.x) {
        int e0 = g_off[n], e1 = g_off[n + 1];
        float p = 0.f;
        for (int e = e0 + s; e < e1; e += 8)
            p += x[g_esrc[e] * IN_DIM + k];
        red[t] = p;
        __syncthreads();
        if (t < 16) {
            float a = 0.f;
            #pragma unroll
            for (int j = 0; j < 8; j++) a += red[j * 16 + t];
            sagg[t] = a * g_invdeg[n];
            sx[t] = x[n * IN_DIM + t];
        }
        __syncthreads();
        float acc = sb[t];
        #pragma unroll
        for (int kk = 0; kk < IN_DIM; kk++)
            acc += sagg[kk] * sWl[kk * HID + t] + sx[kk] * sWr[kk * HID + t];
        hout[n * HID + t] = fmaxf(acc, 0.f);
        __syncthreads();
    }
}

// ---------------- 128-d mean aggregation via CSR (one block = one node) ----------------
__global__ void k_agg128(const float* __restrict__ hin, float* __restrict__ aggout) {
    int n = blockIdx.x;
    int t = threadIdx.x;
    int e0 = g_off[n], e1 = g_off[n + 1];
    float s0 = 0.f, s1 = 0.f;
    int e = e0;
    for (; e + 1 < e1; e += 2) {
        int i0 = g_esrc[e], i1 = g_esrc[e + 1];
        s0 += hin[i0 * HID + t];
        s1 += hin[i1 * HID + t];
    }
    if (e < e1) s0 += hin[g_esrc[e] * HID + t];
    aggout[n * HID + t] = (s0 + s1) * g_invdeg[n];
}

// ---------------- dual GEMM: out = relu([agg|h] @ [Wl|Wr]^T + b) ----------------
// Tile 64 rows x 128 cols. 256 threads, 4x8 per thread. k chunked by 32;
// chunks 0-3 use (Aagg, Wl), chunks 4-7 use (Aself, Wr). Static smem ~26KB.
#define TK  32
#define SWS 132   // 132*4 = 528 bytes, multiple of 16 -> float4-aligned rows
#define SAS 33

__global__ void __launch_bounds__(256)
k_gemm_dual(const float* __restrict__ Aagg, const float* __restrict__ Aself,
            const float* __restrict__ Wl, const float* __restrict__ Wr,
            const float* __restrict__ b, float* __restrict__ out) {
    __shared__ float sW[TK * SWS];   // sW[kk][o]
    __shared__ float sA[64 * SAS];   // sA[row][kk]
    int t = threadIdx.x;
    int row0 = (t >> 4) << 2;        // 0..60 step 4
    int col0 = (t & 15) << 3;        // 0..120 step 8
    int nbase = blockIdx.x * 64;

    float acc[4][8];
    #pragma unroll
    for (int c = 0; c < 8; c++) {
        float bv = b[col0 + c];
        #pragma unroll
        for (int r = 0; r < 4; r++) acc[r][c] = bv;
    }

    for (int ch = 0; ch < 8; ch++) {
        const float* Wsrc = (ch < 4) ? Wl : Wr;
        const float* Asrc = (ch < 4) ? Aagg : Aself;
        int koff = (ch & 3) * TK;
        __syncthreads();   // protect previous iteration's smem reads
        // stage W chunk [32 k x 128 o], transposed
        for (int i = t; i < 4096; i += 256) {
            int o = i >> 5, kk = i & 31;
            sW[kk * SWS + o] = Wsrc[o * HID + koff + kk];
        }
        // stage A chunk [64 rows x 32 k]
        for (int i = t; i < 512; i += 256) {
            int row = i >> 3, q = i & 7;
            int n = nbase + row;
            float4 v = make_float4(0.f, 0.f, 0.f, 0.f);
            if (n < N_NODES)
                v = *(const float4*)(Asrc + n * HID + koff + q * 4);
            sA[row * SAS + q * 4 + 0] = v.x;
            sA[row * SAS + q * 4 + 1] = v.y;
            sA[row * SAS + q * 4 + 2] = v.z;
            sA[row * SAS + q * 4 + 3] = v.w;
        }
        __syncthreads();

        #pragma unroll 8
        for (int kk = 0; kk < TK; kk++) {
            float4 w0 = *(const float4*)(sW + kk * SWS + col0);
            float4 w1 = *(const float4*)(sW + kk * SWS + col0 + 4);
            #pragma unroll
            for (int r = 0; r < 4; r++) {
                float a = sA[(row0 + r) * SAS + kk];
                acc[r][0] += a * w0.x; acc[r][1] += a * w0.y;
                acc[r][2] += a * w0.z; acc[r][3] += a * w0.w;
                acc[r][4] += a * w1.x; acc[r][5] += a * w1.y;
                acc[r][6] += a * w1.z; acc[r][7] += a * w1.w;
            }
        }
    }

    #pragma unroll
    for (int r = 0; r < 4; r++) {
        int n = nbase + row0 + r;
        if (n < N_NODES) {
            float4 o1 = make_float4(fmaxf(acc[r][0], 0.f), fmaxf(acc[r][1], 0.f),
                                    fmaxf(acc[r][2], 0.f), fmaxf(acc[r][3], 0.f));
            float4 o2 = make_float4(fmaxf(acc[r][4], 0.f), fmaxf(acc[r][5], 0.f),
                                    fmaxf(acc[r][6], 0.f), fmaxf(acc[r][7], 0.f));
            *(float4*)(out + n * HID + col0) = o1;
            *(float4*)(out + n * HID + col0 + 4) = o2;
        }
    }
}

// ---------------- head: out = h @ Wh^T + bh (one warp per node) ----------------
__global__ void k_head(const float* __restrict__ hin,
                       const float* __restrict__ Wh,
                       const float* __restrict__ bh,
                       float* __restrict__ out) {
    __shared__ float sWh[OUT_DIM * HID];
    __shared__ float sbh[OUT_DIM];
    int t = threadIdx.x;
    for (int i = t; i < OUT_DIM * HID; i += 128) sWh[i] = Wh[i];
    if (t < OUT_DIM) sbh[t] = bh[t];
    __syncthreads();
    int lane = t & 31;
    int n = blockIdx.x * 4 + (t >> 5);
    if (n >= N_NODES) return;   // whole warp exits together (n is per-warp)
    float4 hv = *(const float4*)(hin + n * HID + lane * 4);
    float p[OUT_DIM];
    #pragma unroll
    for (int o = 0; o < OUT_DIM; o++) {
        const float* wr = sWh + o * HID + lane * 4;
        p[o] = hv.x * wr[0] + hv.y * wr[1] + hv.z * wr[2] + hv.w * wr[3];
    }
    #pragma unroll
    for (int o = 0; o < OUT_DIM; o++)
        #pragma unroll
        for (int off = 16; off > 0; off >>= 1)
            p[o] += __shfl_down_sync(0xffffffffu, p[o], off);
    if (lane == 0) {
        float4 r = make_float4(p[0] + sbh[0], p[1] + sbh[1],
                               p[2] + sbh[2], p[3] + sbh[3]);
        *(float4*)(out + n * OUT_DIM) = r;
    }
}

// ---------------- launch ----------------
extern "C" void kernel_launch(void* const* d_in, const int* in_sizes, int n_in,
                              void* d_out, int out_size) {
    // ---- size-signature input identification (robust to any permutation) ----
    int ix = -1, ie = -1, iwh = -1, ibh = -1;
    int w1[2] = {-1, -1}; int nw1 = 0;
    int w2[4] = {-1, -1, -1, -1}; int nw2 = 0;
    int bb[3] = {-1, -1, -1}; int nb = 0;
    for (int i = 0; i < n_in; i++) {
        int s = in_sizes[i];
        if      (s == 800000)  ix = i;
        else if (s == 512)     iwh = i;
        else if (s == 4)       ibh = i;
        else if (s == 2048)    { if (nw1 < 2) w1[nw1++] = i; }
        else if (s == 16384)   { if (nw2 < 4) w2[nw2++] = i; }
        else if (s == 128)     { if (nb  < 3) bb[nb++]  = i; }
        else if (s == 1200000 || s == 2400000) ie = i;
    }
    bool ok = (ix >= 0) && (ie >= 0) && (iwh >= 0) && (ibh >= 0) &&
              (nw1 == 2) && (nw2 == 4) && (nb == 3);

    int iwl1, iwr1, iwl2, iwr2, iwl3, iwr3, ib1, ib2, ib3;
    if (ok) {
        iwl1 = w1[0]; iwr1 = w1[1];            // Wl1 precedes Wr1 in dict & alpha order
        ib1 = bb[0]; ib2 = bb[1]; ib3 = bb[2]; // zeros — order irrelevant
        // Alphabetical order puts Wh BEFORE the 16384s ([Wl2,Wl3,Wr2,Wr3]);
        // dict order puts Wh AFTER them ([Wl2,Wr2,Wl3,Wr3]).
        if (iwh < w2[0]) { iwl2 = w2[0]; iwl3 = w2[1]; iwr2 = w2[2]; iwr3 = w2[3]; }
        else             { iwl2 = w2[0]; iwr2 = w2[1]; iwl3 = w2[2]; iwr3 = w2[3]; }
    } else {
        ix = 0; ie = 1; iwl1 = 2; iwr1 = 3; ib1 = 4; iwl2 = 5; iwr2 = 6; ib2 = 7;
        iwl3 = 8; iwr3 = 9; ib3 = 10; iwh = 11; ibh = 12;
    }

    const float* x   = (const float*)d_in[ix];
    const void*  ei  = d_in[ie];
    const float* Wl1 = (const float*)d_in[iwl1];
    const float* Wr1 = (const float*)d_in[iwr1];
    const float* b1  = (const float*)d_in[ib1];
    const float* Wl2 = (const float*)d_in[iwl2];
    const float* Wr2 = (const float*)d_in[iwr2];
    const float* b2  = (const float*)d_in[ib2];
    const float* Wl3 = (const float*)d_in[iwl3];
    const float* Wr3 = (const float*)d_in[iwr3];
    const float* b3  = (const float*)d_in[ib3];
    const float* Wh  = (const float*)d_in[iwh];
    const float* bh  = (const float*)d_in[ibh];
    float* out = (float*)d_out;

    // THE FIX: resolve device addresses of __device__ scratch symbols.
    // (Passing the symbol directly from host code passes the host-side shadow
    //  address — silent UB that zeroed/poisoned the whole downstream pipeline.)
    float *hA = nullptr, *hB = nullptr, *agg = nullptr;
    cudaGetSymbolAddress((void**)&hA,  g_hA);
    cudaGetSymbolAddress((void**)&hB,  g_hB);
    cudaGetSymbolAddress((void**)&agg, g_agg);

    // CSR build
    k_detect<<<1, 32>>>((const unsigned int*)ei);
    k_zero<<<(N_NODES + 255) / 256, 256>>>();
    k_count<<<(N_EDGES + 255) / 256, 256>>>(ei);
    k_scan<<<1, 512>>>();
    k_invdeg<<<(N_NODES + 255) / 256, 256>>>();
    k_fill<<<(N_EDGES + 255) / 256, 256>>>(ei);

    // layer 1: x(16) -> hA(128)
    k_layer1<<<1184, 128>>>(x, Wl1, Wr1, b1, hA);

    // layer 2: hA -> hB
    k_agg128<<<N_NODES, 128>>>(hA, agg);
    k_gemm_dual<<<NT_GEMM, 256>>>(agg, hA, Wl2, Wr2, b2, hB);

    // layer 3: hB -> hA
    k_agg128<<<N_NODES, 128>>>(hB, agg);
    k_gemm_dual<<<NT_GEMM, 256>>>(agg, hB, Wl3, Wr3, b3, hA);

    // head
    k_head<<<(N_NODES + 3) / 4, 128>>>(hA, Wh, bh, out);
}

// round 7
// speedup vs baseline: 1.1177x; 1.1177x over previous
#include <cuda_runtime.h>
#include <stdint.h>

#define N_NODES 50000
#define N_EDGES 600000
#define IN_DIM  16
#define HID     128
#define OUT_DIM 4
#define NT_GEMM ((N_NODES + 63) / 64)   // 782 row-tiles of 64
#define NB      ((N_NODES + 255) / 256) // 196 scan blocks

// ---------------- device scratch (no runtime allocation allowed) ----------------
__device__ int   g_deg[N_NODES];
__device__ int   g_cur[N_NODES];
__device__ int   g_off[N_NODES + 1];
__device__ int   g_esrc[N_EDGES];
__device__ float g_invdeg[N_NODES];
__device__ float g_agg[N_NODES * HID];
__device__ float g_hA[N_NODES * HID];
__device__ float g_hB[N_NODES * HID];
__device__ int   g_bsum[NB];
__device__ int   g_bpre[NB];
__device__ int   g_is64;

// ---------------- f32x2 helpers (Blackwell packed fp32) ----------------
typedef unsigned long long ull;

__device__ __forceinline__ ull packf2(float x, float y) {
    ull r; asm("mov.b64 %0, {%1, %2};" : "=l"(r) : "f"(x), "f"(y)); return r;
}
__device__ __forceinline__ void ffma2(ull& d, ull a, ull b) {
    asm("fma.rn.f32x2 %0, %1, %2, %0;" : "+l"(d) : "l"(a), "l"(b));
}
__device__ __forceinline__ float2 unpackf2(ull v) {
    float2 r; asm("mov.b64 {%0, %1}, %2;" : "=f"(r.x), "=f"(r.y) : "l"(v)); return r;
}

// ---------------- dtype detection for edge_index (int64 vs int32) ----------------
__global__ void k_detect(const unsigned int* __restrict__ ei32) {
    if (threadIdx.x == 0) {
        unsigned int acc = 0;
        #pragma unroll
        for (int i = 0; i < 64; i++) acc |= ei32[2 * i + 1];
        g_is64 = (acc == 0) ? 1 : 0;
    }
}

__device__ __forceinline__ int load_edge(const void* ei, int idx, int is64) {
    if (is64) return (int)((const long long*)ei)[idx];
    return ((const int*)ei)[idx];
}

// ---------------- CSR build ----------------
__global__ void k_zero() {
    int i = blockIdx.x * blockDim.x + threadIdx.x;
    if (i < N_NODES) { g_deg[i] = 0; g_cur[i] = 0; }
}

__global__ void k_count(const void* __restrict__ ei) {
    int e = blockIdx.x * blockDim.x + threadIdx.x;
    if (e >= N_EDGES) return;
    int is64 = g_is64;
    int d = load_edge(ei, N_EDGES + e, is64);
    if ((unsigned)d < (unsigned)N_NODES)
        atomicAdd(&g_deg[d], 1);
}

// multi-block scan, stage 1: per-block sums (196 blocks x 256)
__global__ void k_blocksum() {
    int t = threadIdx.x;
    int i = blockIdx.x * 256 + t;
    int v = (i < N_NODES) ? g_deg[i] : 0;
    #pragma unroll
    for (int o = 16; o; o >>= 1) v += __shfl_down_sync(0xffffffffu, v, o);
    __shared__ int ws[8];
    if ((t & 31) == 0) ws[t >> 5] = v;
    __syncthreads();
    if (t < 8) {
        int s = ws[t];
        #pragma unroll
        for (int o = 4; o; o >>= 1) s += __shfl_down_sync(0x000000ffu, s, o);
        if (t == 0) g_bsum[blockIdx.x] = s;
    }
}

// stage 2: exclusive scan of 196 block sums (1 block x 256)
__global__ void k_scanb() {
    int t = threadIdx.x, lane = t & 31, w = t >> 5;
    int v = (t < NB) ? g_bsum[t] : 0;
    int x = v;
    #pragma unroll
    for (int d = 1; d < 32; d <<= 1) {
        int y = __shfl_up_sync(0xffffffffu, x, d);
        if (lane >= d) x += y;
    }
    __shared__ int ws[8];
    if (lane == 31) ws[w] = x;
    __syncthreads();
    if (t < 8) {
        int s = ws[t], xs = s;
        #pragma unroll
        for (int d = 1; d < 8; d <<= 1) {
            int y = __shfl_up_sync(0x000000ffu, xs, d);
            if (t >= d) xs += y;
        }
        ws[t] = xs - s;   // exclusive prefix of warp totals
    }
    __syncthreads();
    int incl = ws[w] + x;
    if (t < NB) g_bpre[t] = incl - v;
    if (t == 255) g_off[N_NODES] = incl;   // grand total
}

// stage 3: per-block local scan + base, plus invdeg (196 blocks x 256)
__global__ void k_offsets() {
    int t = threadIdx.x, lane = t & 31, w = t >> 5;
    int i = blockIdx.x * 256 + t;
    int v = (i < N_NODES) ? g_deg[i] : 0;
    int x = v;
    #pragma unroll
    for (int d = 1; d < 32; d <<= 1) {
        int y = __shfl_up_sync(0xffffffffu, x, d);
        if (lane >= d) x += y;
    }
    __shared__ int ws[8];
    if (lane == 31) ws[w] = x;
    __syncthreads();
    if (t < 8) {
        int s = ws[t], xs = s;
        #pragma unroll
        for (int d = 1; d < 8; d <<= 1) {
            int y = __shfl_up_sync(0x000000ffu, xs, d);
            if (t >= d) xs += y;
        }
        ws[t] = xs - s;
    }
    __syncthreads();
    if (i < N_NODES) {
        g_off[i] = g_bpre[blockIdx.x] + ws[w] + (x - v);
        g_invdeg[i] = 1.0f / (float)(v > 0 ? v : 1);
    }
}

__global__ void k_fill(const void* __restrict__ ei) {
    int e = blockIdx.x * blockDim.x + threadIdx.x;
    if (e >= N_EDGES) return;
    int is64 = g_is64;
    int d = load_edge(ei, N_EDGES + e, is64);
    if ((unsigned)d >= (unsigned)N_NODES) return;
    int s = load_edge(ei, e, is64);
    if ((unsigned)s >= (unsigned)N_NODES) s = 0;
    int p = g_off[d] + atomicAdd(&g_cur[d], 1);
    if ((unsigned)p < (unsigned)N_EDGES)
        g_esrc[p] = s;
}

// ---------------- layer 1: aggregate x (16-d) + dual GEMM 16->128 + relu ----------------
__global__ void k_layer1(const float* __restrict__ x,
                         const float* __restrict__ Wl,
                         const float* __restrict__ Wr,
                         const float* __restrict__ b,
                         float* __restrict__ hout) {
    __shared__ float sWl[IN_DIM * HID], sWr[IN_DIM * HID], sb[HID];
    __shared__ float red[128], sagg[IN_DIM], sx[IN_DIM];
    int t = threadIdx.x;
    for (int i = t; i < HID * IN_DIM; i += 128) {
        int o = i >> 4, k = i & 15;
        sWl[k * HID + o] = Wl[i];   // sW[k][o] = W[o][k]
        sWr[k * HID + o] = Wr[i];
    }
    sb[t] = b[t];
    __syncthreads();
    int k = t & 15, s = t >> 4;
    for (int n = blockIdx.x; n < N_NODES; n += gridDim.x) {
        int e0 = g_off[n], e1 = g_off[n + 1];
        float p = 0.f;
        for (int e = e0 + s; e < e1; e += 8)
            p += x[g_esrc[e] * IN_DIM + k];
        red[t] = p;
        __syncthreads();
        if (t < 16) {
            float a = 0.f;
            #pragma unroll
            for (int j = 0; j < 8; j++) a += red[j * 16 + t];
            sagg[t] = a * g_invdeg[n];
            sx[t] = x[n * IN_DIM + t];
        }
        __syncthreads();
        float acc = sb[t];
        #pragma unroll
        for (int kk = 0; kk < IN_DIM; kk++)
            acc += sagg[kk] * sWl[kk * HID + t] + sx[kk] * sWr[kk * HID + t];
        hout[n * HID + t] = fmaxf(acc, 0.f);
        __syncthreads();
    }
}

// ---------------- 128-d mean aggregation via CSR (one block = one node) ----------------
__global__ void k_agg128(const float* __restrict__ hin, float* __restrict__ aggout) {
    int n = blockIdx.x;
    int t = threadIdx.x;
    int e0 = g_off[n], e1 = g_off[n + 1];
    float s0 = 0.f, s1 = 0.f;
    int e = e0;
    for (; e + 1 < e1; e += 2) {
        int i0 = g_esrc[e], i1 = g_esrc[e + 1];
        s0 += hin[i0 * HID + t];
        s1 += hin[i1 * HID + t];
    }
    if (e < e1) s0 += hin[g_esrc[e] * HID + t];
    aggout[n * HID + t] = (s0 + s1) * g_invdeg[n];
}

// ---------------- dual GEMM: out = relu([agg|h] @ [Wl|Wr]^T + b) ----------------
// Tile 64 rows x 128 cols, 256 threads, 4x8 per thread, fma.rn.f32x2 inner loop.
// k chunked by 32; chunks 0-3 use (Aagg, Wl), chunks 4-7 use (Aself, Wr).
#define TK  32
#define SWS 132   // 132*4 = 528 B row stride, multiple of 16
#define SAS 36    // 36*4 = 144 B row stride, multiple of 16

__global__ void __launch_bounds__(256)
k_gemm_dual(const float* __restrict__ Aagg, const float* __restrict__ Aself,
            const float* __restrict__ Wl, const float* __restrict__ Wr,
            const float* __restrict__ b, float* __restrict__ out) {
    __shared__ float sW[TK * SWS];   // sW[kk][o]
    __shared__ float sA[64 * SAS];   // sA[row][kk]
    int t = threadIdx.x;
    int row0 = (t >> 4) << 2;        // 0..60 step 4
    int col0 = (t & 15) << 3;        // 0..120 step 8
    int nbase = blockIdx.x * 64;

    ull acc[4][4];                   // packed pairs: 4 rows x 8 cols
    #pragma unroll
    for (int c = 0; c < 4; c++) {
        ull bv = packf2(b[col0 + 2 * c], b[col0 + 2 * c + 1]);
        #pragma unroll
        for (int r = 0; r < 4; r++) acc[r][c] = bv;
    }

    for (int ch = 0; ch < 8; ch++) {
        const float* Wsrc = (ch < 4) ? Wl : Wr;
        const float* Asrc = (ch < 4) ? Aagg : Aself;
        int koff = (ch & 3) * TK;
        __syncthreads();   // protect previous iteration's smem reads
        // stage W chunk [32 k x 128 o], transposed
        for (int i = t; i < 4096; i += 256) {
            int o = i >> 5, kk = i & 31;
            sW[kk * SWS + o] = Wsrc[o * HID + koff + kk];
        }
        // stage A chunk [64 rows x 32 k]
        for (int i = t; i < 512; i += 256) {
            int row = i >> 3, q = i & 7;
            int n = nbase + row;
            float4 v = make_float4(0.f, 0.f, 0.f, 0.f);
            if (n < N_NODES)
                v = *(const float4*)(Asrc + n * HID + koff + q * 4);
            *(float4*)(sA + row * SAS + q * 4) = v;
        }
        __syncthreads();

        #pragma unroll
        for (int kk = 0; kk < TK; kk += 4) {
            float4 a4[4];
            #pragma unroll
            for (int r = 0; r < 4; r++)
                a4[r] = *(const float4*)(sA + (row0 + r) * SAS + kk);
            #pragma unroll
            for (int j = 0; j < 4; j++) {
                ulonglong2 wa = *(const ulonglong2*)(sW + (kk + j) * SWS + col0);
                ulonglong2 wb = *(const ulonglong2*)(sW + (kk + j) * SWS + col0 + 4);
                #pragma unroll
                for (int r = 0; r < 4; r++) {
                    float a = (j == 0) ? a4[r].x : (j == 1) ? a4[r].y
                            : (j == 2) ? a4[r].z : a4[r].w;
                    ull a2 = packf2(a, a);
                    ffma2(acc[r][0], wa.x, a2);
                    ffma2(acc[r][1], wa.y, a2);
                    ffma2(acc[r][2], wb.x, a2);
                    ffma2(acc[r][3], wb.y, a2);
                }
            }
        }
    }

    #pragma unroll
    for (int r = 0; r < 4; r++) {
        int n = nbase + row0 + r;
        if (n < N_NODES) {
            float2 v0 = unpackf2(acc[r][0]);
            float2 v1 = unpackf2(acc[r][1]);
            float2 v2 = unpackf2(acc[r][2]);
            float2 v3 = unpackf2(acc[r][3]);
            float4 o1 = make_float4(fmaxf(v0.x, 0.f), fmaxf(v0.y, 0.f),
                                    fmaxf(v1.x, 0.f), fmaxf(v1.y, 0.f));
            float4 o2 = make_float4(fmaxf(v2.x, 0.f), fmaxf(v2.y, 0.f),
                                    fmaxf(v3.x, 0.f), fmaxf(v3.y, 0.f));
            *(float4*)(out + n * HID + col0) = o1;
            *(float4*)(out + n * HID + col0 + 4) = o2;
        }
    }
}

// ---------------- head: out = h @ Wh^T + bh (one warp per node) ----------------
__global__ void k_head(const float* __restrict__ hin,
                       const float* __restrict__ Wh,
                       const float* __restrict__ bh,
                       float* __restrict__ out) {
    __shared__ float sWh[OUT_DIM * HID];
    __shared__ float sbh[OUT_DIM];
    int t = threadIdx.x;
    for (int i = t; i < OUT_DIM * HID; i += 128) sWh[i] = Wh[i];
    if (t < OUT_DIM) sbh[t] = bh[t];
    __syncthreads();
    int lane = t & 31;
    int n = blockIdx.x * 4 + (t >> 5);
    if (n >= N_NODES) return;   // whole warp exits together (n is per-warp)
    float4 hv = *(const float4*)(hin + n * HID + lane * 4);
    float p[OUT_DIM];
    #pragma unroll
    for (int o = 0; o < OUT_DIM; o++) {
        const float* wr = sWh + o * HID + lane * 4;
        p[o] = hv.x * wr[0] + hv.y * wr[1] + hv.z * wr[2] + hv.w * wr[3];
    }
    #pragma unroll
    for (int o = 0; o < OUT_DIM; o++)
        #pragma unroll
        for (int off = 16; off > 0; off >>= 1)
            p[o] += __shfl_down_sync(0xffffffffu, p[o], off);
    if (lane == 0) {
        float4 r = make_float4(p[0] + sbh[0], p[1] + sbh[1],
                               p[2] + sbh[2], p[3] + sbh[3]);
        *(float4*)(out + n * OUT_DIM) = r;
    }
}

// ---------------- launch ----------------
extern "C" void kernel_launch(void* const* d_in, const int* in_sizes, int n_in,
                              void* d_out, int out_size) {
    // ---- size-signature input identification (robust to any permutation) ----
    int ix = -1, ie = -1, iwh = -1, ibh = -1;
    int w1[2] = {-1, -1}; int nw1 = 0;
    int w2[4] = {-1, -1, -1, -1}; int nw2 = 0;
    int bb[3] = {-1, -1, -1}; int nb = 0;
    for (int i = 0; i < n_in; i++) {
        int s = in_sizes[i];
        if      (s == 800000)  ix = i;
        else if (s == 512)     iwh = i;
        else if (s == 4)       ibh = i;
        else if (s == 2048)    { if (nw1 < 2) w1[nw1++] = i; }
        else if (s == 16384)   { if (nw2 < 4) w2[nw2++] = i; }
        else if (s == 128)     { if (nb  < 3) bb[nb++]  = i; }
        else if (s == 1200000 || s == 2400000) ie = i;
    }
    bool ok = (ix >= 0) && (ie >= 0) && (iwh >= 0) && (ibh >= 0) &&
              (nw1 == 2) && (nw2 == 4) && (nb == 3);

    int iwl1, iwr1, iwl2, iwr2, iwl3, iwr3, ib1, ib2, ib3;
    if (ok) {
        iwl1 = w1[0]; iwr1 = w1[1];
        ib1 = bb[0]; ib2 = bb[1]; ib3 = bb[2];
        if (iwh < w2[0]) { iwl2 = w2[0]; iwl3 = w2[1]; iwr2 = w2[2]; iwr3 = w2[3]; }
        else             { iwl2 = w2[0]; iwr2 = w2[1]; iwl3 = w2[2]; iwr3 = w2[3]; }
    } else {
        ix = 0; ie = 1; iwl1 = 2; iwr1 = 3; ib1 = 4; iwl2 = 5; iwr2 = 6; ib2 = 7;
        iwl3 = 8; iwr3 = 9; ib3 = 10; iwh = 11; ibh = 12;
    }

    const float* x   = (const float*)d_in[ix];
    const void*  ei  = d_in[ie];
    const float* Wl1 = (const float*)d_in[iwl1];
    const float* Wr1 = (const float*)d_in[iwr1];
    const float* b1  = (const float*)d_in[ib1];
    const float* Wl2 = (const float*)d_in[iwl2];
    const float* Wr2 = (const float*)d_in[iwr2];
    const float* b2  = (const float*)d_in[ib2];
    const float* Wl3 = (const float*)d_in[iwl3];
    const float* Wr3 = (const float*)d_in[iwr3];
    const float* b3  = (const float*)d_in[ib3];
    const float* Wh  = (const float*)d_in[iwh];
    const float* bh  = (const float*)d_in[ibh];
    float* out = (float*)d_out;

    // Resolve device addresses of __device__ scratch symbols (host-side symbol
    // decay passes the host shadow address — the round-5 bug).
    float *hA = nullptr, *hB = nullptr, *agg = nullptr;
    cudaGetSymbolAddress((void**)&hA,  g_hA);
    cudaGetSymbolAddress((void**)&hB,  g_hB);
    cudaGetSymbolAddress((void**)&agg, g_agg);

    // CSR build (multi-block scan)
    k_detect<<<1, 32>>>((const unsigned int*)ei);
    k_zero<<<NB, 256>>>();
    k_count<<<(N_EDGES + 255) / 256, 256>>>(ei);
    k_blocksum<<<NB, 256>>>();
    k_scanb<<<1, 256>>>();
    k_offsets<<<NB, 256>>>();
    k_fill<<<(N_EDGES + 255) / 256, 256>>>(ei);

    // layer 1: x(16) -> hA(128)
    k_layer1<<<1184, 128>>>(x, Wl1, Wr1, b1, hA);

    // layer 2: hA -> hB
    k_agg128<<<N_NODES, 128>>>(hA, agg);
    k_gemm_dual<<<NT_GEMM, 256>>>(agg, hA, Wl2, Wr2, b2, hB);

    // layer 3: hB -> hA
    k_agg128<<<N_NODES, 128>>>(hB, agg);
    k_gemm_dual<<<NT_GEMM, 256>>>(agg, hB, Wl3, Wr3, b3, hA);

    // head
    k_head<<<(N_NODES + 3) / 4, 128>>>(hA, Wh, bh, out);
}